// round 11
// baseline (speedup 1.0000x reference)
#include <cuda_runtime.h>
#include <cuda_fp16.h>
#include <math.h>
#include <stdint.h>

#define NN 8192
#define FIN 256
#define FOUT 64
#define LRALPHA 0.2f

#define BM 128
#define BK 64
#define NB 72               // B n-rows: 64 out + ones(64) + zeros(65..71)
#define ASTR 72             // A SMEM stride (halves)
#define BSTR 72             // B SMEM stride (halves)
#define NSPLIT 4
#define JCHUNK (NN / NSPLIT)        // 2048
#define NTILES (JCHUNK / BK)        // 32
#define PART_STRIDE 72

// ---- persistent scratch (no allocations allowed) ----
__device__ __align__(16) __half g_Wht[(size_t)NB * NN];   // transposed fp16 Wh + ones/zeros
__device__ __align__(16) float4 g_rowc[NN];  // (f1, exp(f1-m), exp(.2f1-m), 0)
__device__ __align__(16) float4 g_colc[NN];  // (f2, exp(f2),   exp(.2f2),   0)
__device__ float g_f1[NN];
__device__ float g_f2[NN];
__device__ unsigned int g_m2key = 0u;        // reset at end of k_reduce (prev replay)
__device__ __align__(16) float g_part[(size_t)NSPLIT * NN * PART_STRIDE];

__device__ __forceinline__ float elu_f(float x) {
    return x > 0.f ? x : expm1f(x);
}
__device__ __forceinline__ unsigned int fkey(float x) {
    unsigned int b = __float_as_uint(x);
    return (b & 0x80000000u) ? ~b : (b | 0x80000000u);
}
__device__ __forceinline__ float fdecode(unsigned int k) {
    return __uint_as_float((k & 0x80000000u) ? (k & 0x7fffffffu) : ~k);
}
__device__ __forceinline__ void cp_async16(uint32_t smem_addr, const void* gptr) {
    asm volatile("cp.async.cg.shared.global [%0], [%1], 16;\n"
                 :: "r"(smem_addr), "l"(gptr));
}
__device__ __forceinline__ void cp_commit() {
    asm volatile("cp.async.commit_group;\n" ::: "memory");
}
__device__ __forceinline__ void cp_wait1() {
    asm volatile("cp.async.wait_group 1;\n" ::: "memory");
}
__device__ __forceinline__ void cp_wait0() {
    asm volatile("cp.async.wait_group 0;\n" ::: "memory");
}
__device__ __forceinline__ void ldsm_x4(uint32_t& r0, uint32_t& r1,
                                        uint32_t& r2, uint32_t& r3, uint32_t a) {
    asm volatile("ldmatrix.sync.aligned.m8n8.x4.shared.b16 {%0,%1,%2,%3}, [%4];"
                 : "=r"(r0), "=r"(r1), "=r"(r2), "=r"(r3) : "r"(a));
}
__device__ __forceinline__ void ldsm_x2(uint32_t& r0, uint32_t& r1, uint32_t a) {
    asm volatile("ldmatrix.sync.aligned.m8n8.x2.shared.b16 {%0,%1}, [%2];"
                 : "=r"(r0), "=r"(r1) : "r"(a));
}

// ---------------------------------------------------------------------------
// Kernel 1: Wh = h @ W (fp32), transposed fp16 store to g_Wht; rows 64..71 =
// ones/zeros.  Fused epilogue: f1 = Wh.a1, f2 = Wh.a2, M2 = max f2 (atomicMax).
// Block = 64 rows, grid 128.  Thread = (rs = t>>4: 4 rows) x (cg = t&15: 4 cols).
// LDS traffic 2 B/FFMA (was 5).
// ---------------------------------------------------------------------------
__global__ __launch_bounds__(256) void k_gemm_wh(
    const float* __restrict__ h, const float* __restrict__ W,
    const float* __restrict__ a)
{
    __shared__ float hs[64][68];
    __shared__ float wt2[64][68];
    __shared__ unsigned int smax;
    float* ts = &hs[0][0];         // alias: transpose staging [c][r], stride 65

    int t = threadIdx.x;
    int i0 = blockIdx.x * 64;
    int cg = t & 15;               // col-group: cols 4cg..4cg+3
    int rs = t >> 4;               // row-slot : rows 4rs..4rs+3

    if (t == 0) smax = 0u;

    float4 acc[4];
#pragma unroll
    for (int q = 0; q < 4; q++) acc[q] = make_float4(0.f, 0.f, 0.f, 0.f);

    for (int kt = 0; kt < FIN; kt += 64) {
        __syncthreads();
#pragma unroll
        for (int it = 0; it < 16; it++) {
            int l = t + 256 * it;
            int r = l >> 6, c = l & 63;
            hs[r][c]  = h[(size_t)(i0 + r) * FIN + kt + c];
            wt2[r][c] = W[(size_t)(kt + r) * FOUT + c];
        }
        __syncthreads();
#pragma unroll
        for (int k4 = 0; k4 < 16; k4++) {
            float4 w0 = *(const float4*)&wt2[k4 * 4 + 0][cg * 4];
            float4 w1 = *(const float4*)&wt2[k4 * 4 + 1][cg * 4];
            float4 w2 = *(const float4*)&wt2[k4 * 4 + 2][cg * 4];
            float4 w3 = *(const float4*)&wt2[k4 * 4 + 3][cg * 4];
#pragma unroll
            for (int q = 0; q < 4; q++) {
                float4 hv = *(const float4*)&hs[rs * 4 + q][k4 * 4];  // broadcast
                acc[q].x += hv.x * w0.x + hv.y * w1.x + hv.z * w2.x + hv.w * w3.x;
                acc[q].y += hv.x * w0.y + hv.y * w1.y + hv.z * w2.y + hv.w * w3.y;
                acc[q].z += hv.x * w0.z + hv.y * w1.z + hv.z * w2.z + hv.w * w3.z;
                acc[q].w += hv.x * w0.w + hv.y * w1.w + hv.z * w2.w + hv.w * w3.w;
            }
        }
    }

    // ---- fused f1/f2: per-row dots with a1/a2, reduce across the 16 cg lanes
    {
        float4 a1v = *(const float4*)&a[4 * cg];
        float4 a2v = *(const float4*)&a[64 + 4 * cg];
        float s1[4], s2[4];
#pragma unroll
        for (int q = 0; q < 4; q++) {
            s1[q] = acc[q].x * a1v.x + acc[q].y * a1v.y
                  + acc[q].z * a1v.z + acc[q].w * a1v.w;
            s2[q] = acc[q].x * a2v.x + acc[q].y * a2v.y
                  + acc[q].z * a2v.z + acc[q].w * a2v.w;
        }
#pragma unroll
        for (int o = 8; o > 0; o >>= 1) {
#pragma unroll
            for (int q = 0; q < 4; q++) {
                s1[q] += __shfl_xor_sync(0xffffffffu, s1[q], o);
                s2[q] += __shfl_xor_sync(0xffffffffu, s2[q], o);
            }
        }
        if (cg == 0) {
            float mm = -1e30f;
#pragma unroll
            for (int q = 0; q < 4; q++) {
                g_f1[i0 + rs * 4 + q] = s1[q];
                g_f2[i0 + rs * 4 + q] = s2[q];
                mm = fmaxf(mm, s2[q]);
            }
            atomicMax(&smax, fkey(mm));
        }
    }
    __syncthreads();               // hs free; smax complete
    if (t == 0) atomicMax(&g_m2key, smax);

    // ---- stage transpose ts[c][r] (stride 65), then fp16 write
#pragma unroll
    for (int q = 0; q < 4; q++) {
        ts[(4 * cg + 0) * 65 + rs * 4 + q] = acc[q].x;
        ts[(4 * cg + 1) * 65 + rs * 4 + q] = acc[q].y;
        ts[(4 * cg + 2) * 65 + rs * 4 + q] = acc[q].z;
        ts[(4 * cg + 3) * 65 + rs * 4 + q] = acc[q].w;
    }
    __syncthreads();
    {
        int c2 = t >> 2, q = t & 3;        // c2: col 0..63, q: 16-row chunk
        __half2 hx[8];
#pragma unroll
        for (int j = 0; j < 8; j++)
            hx[j] = __floats2half2_rn(ts[c2 * 65 + q * 16 + 2 * j],
                                      ts[c2 * 65 + q * 16 + 2 * j + 1]);
        float4* dst = (float4*)&g_Wht[(size_t)c2 * NN + i0 + q * 16];
        dst[0] = *(float4*)&hx[0];
        dst[1] = *(float4*)&hx[4];
    }
    // ones / zero rows 64..71 for this i-slice (2 halves per thread)
    {
        int rz = 64 + (t >> 5), ii = (t & 31) * 2;
        __half v = (rz == 64) ? __float2half(1.0f) : __float2half(0.0f);
        *(__half2*)&g_Wht[(size_t)rz * NN + i0 + ii] = __halves2half2(v, v);
    }
}

// ---------------------------------------------------------------------------
// Kernel 2: row/col exp constants, per-row rescale m_i = lrelu(f1_i + M2).
// ---------------------------------------------------------------------------
__global__ __launch_bounds__(256) void k_consts()
{
    int i = blockIdx.x * 256 + threadIdx.x;
    float M2 = fdecode(g_m2key);
    float f1 = g_f1[i], f2 = g_f2[i];
    float z = f1 + M2;
    float m = (z > 0.f) ? z : LRALPHA * z;
    g_rowc[i] = make_float4(f1, expf(f1 - m), expf(LRALPHA * f1 - m), 0.f);
    g_colc[i] = make_float4(f2, expf(f2), expf(LRALPHA * f2), 0.f);
}

// ---------------------------------------------------------------------------
// Kernel 3: fused masked-softmax attention partials (fp16 m16n8k16 MMA,
// ldmatrix fragments, R6/R10 pipeline schedule — unchanged).
// NB trimmed 80 -> 72: nb==40 warps do 4 n-tiles (their old nt=4 hit pure
// zero padding).  grid = 64 i-blocks x 4 j-splits = 256 CTAs, 2 CTAs/SM.
// SMEM (bytes):
//   [0,     18432)  half  A[128][72]
//   [18432, 39168)  half  B[2][72][72]
//   [39168, 41216)  float4 colcs[2][64]
//   [41216, 43264)  float4 rowcs[128]
// ---------------------------------------------------------------------------
#define SM_A     0
#define SM_B     18432
#define SM_COLC  39168
#define SM_ROWC  41216
#define SMEM_TOTAL 43264
#define BBUF (NB * BSTR * 2)       // 10368

__global__ __launch_bounds__(256, 2) void k_gat(const int* __restrict__ adj)
{
    extern __shared__ __align__(16) char smem[];
    uint32_t sbase = (uint32_t)__cvta_generic_to_shared(smem);

    int t = threadIdx.x;
    int warp = t >> 5, lane = t & 31;
    int i0 = (blockIdx.x >> 2) * BM;
    int split = blockIdx.x & 3;
    int jstart = split * JCHUNK;

    // fixed row constants for the whole CTA
    if (t < 128) ((float4*)(smem + SM_ROWC))[t] = g_rowc[i0 + t];

    // w-gen mapping: warp -> rows 16w..16w+15; lane -> cols 2l, 2l+1
    int wrow0 = warp * 16;
    const int* aptr = adj + (size_t)(i0 + wrow0) * NN + 2 * lane;

    // MMA mapping
    int mb = (warp & 3) * 32;      // 32 rows (2 m-tiles)
    int nb = (warp >> 2) * 40;     // cols: nb=0 -> 0..39 (5 nt), nb=40 -> 40..71 (4 nt)
    int g = lane >> 2, tig = lane & 3;

    // ldmatrix lane addresses
    uint32_t a_ad0 = sbase + SM_A +
        (uint32_t)(((mb + (lane & 15)) * ASTR + ((lane >> 4) << 3)) * 2);
    uint32_t a_ad1 = a_ad0 + 16 * ASTR * 2;
    uint32_t b_off_p = (uint32_t)(((nb + ((lane >> 4) << 3) + (lane & 7)) * BSTR
                                   + (((lane >> 3) & 1) << 3)) * 2);
    uint32_t b_off_2 = (uint32_t)(((nb + 32 + (lane & 7)) * BSTR
                                   + (((lane >> 3) & 1) << 3)) * 2);

    float acc[2][5][4];
#pragma unroll
    for (int m = 0; m < 2; m++)
#pragma unroll
        for (int n = 0; n < 5; n++)
#pragma unroll
            for (int x = 0; x < 4; x++) acc[m][n][x] = 0.f;

    // ---- prologue: B(0)+colc(0) cp.async into buf 0; adj(0) -> registers
    {
#pragma unroll
        for (int it = 0; it < 3; it++) {
            int l = t + 256 * it;
            if (l < 576) {
                int n = l >> 3, kc = l & 7;
                cp_async16(sbase + SM_B + (uint32_t)(n * (BSTR * 2) + kc * 16),
                           &g_Wht[(size_t)n * NN + jstart + kc * 8]);
            }
        }
        if (t < 64)
            cp_async16(sbase + SM_COLC + (uint32_t)t * 16, &g_colc[jstart + t]);
        cp_commit();
    }

    int2 av[16];
#pragma unroll
    for (int r = 0; r < 16; r++)
        av[r] = __ldcs((const int2*)(aptr + (size_t)r * NN + jstart));

    for (int tt = 0; tt < NTILES; tt++) {
        int buf = tt & 1;
        int j0 = jstart + tt * BK;

        // 1. all warps done with MMA(tt-1) (reads B[buf^1]) before refill
        __syncthreads();

        // 2. issue B(tt+1)/colc(tt+1) into buf^1
        if (tt + 1 < NTILES) {
            int jn = j0 + BK;
            uint32_t bd = sbase + SM_B + (uint32_t)(buf ^ 1) * BBUF;
            uint32_t cd = sbase + SM_COLC + (uint32_t)(buf ^ 1) * 1024;
#pragma unroll
            for (int it = 0; it < 3; it++) {
                int l = t + 256 * it;
                if (l < 576) {
                    int n = l >> 3, kc = l & 7;
                    cp_async16(bd + (uint32_t)(n * (BSTR * 2) + kc * 16),
                               &g_Wht[(size_t)n * NN + jn + kc * 8]);
                }
            }
            if (t < 64) cp_async16(cd + (uint32_t)t * 16, &g_colc[jn + t]);
            cp_commit();
            cp_wait1();   // B(tt)/colc(tt) complete; tt+1 in flight
        } else {
            cp_wait0();
        }

        // 3. visibility of B(tt)/colc(tt)
        __syncthreads();

        // 4. w-gen: registers(adj) + smem consts -> fp16 A[128][64]
        {
            const float4* cl = (const float4*)(smem + SM_COLC + buf * 1024);
            float4 cc0 = cl[2 * lane];
            float4 cc1 = cl[2 * lane + 1];
            const float4* rw = (const float4*)(smem + SM_ROWC) + wrow0;
            __half2* adst = (__half2*)(smem + SM_A) + lane;
#pragma unroll
            for (int r = 0; r < 16; r++) {
                float4 rc = rw[r];                 // LDS broadcast
                int2 a2 = av[r];
                float w0 = ((rc.x + cc0.x) > 0.f) ? rc.y * cc0.y : rc.z * cc0.z;
                float w1 = ((rc.x + cc1.x) > 0.f) ? rc.y * cc1.y : rc.z * cc1.z;
                w0 = a2.x ? w0 : 0.f;
                w1 = a2.y ? w1 : 0.f;
                adst[(wrow0 + r) * (ASTR / 2)] = __floats2half2_rn(w0, w1);
            }
        }

        // 5. stream adj(tt+1) into registers (flies over sync + MMA)
        if (tt + 1 < NTILES) {
            int jn = j0 + BK;
#pragma unroll
            for (int r = 0; r < 16; r++)
                av[r] = __ldcs((const int2*)(aptr + (size_t)r * NN + jn));
        }

        // 6. A visible
        __syncthreads();

        // 7. MMA: 4 k-steps x (2 m-tiles x 4/5 n-tiles), ldmatrix fragments
        uint32_t b_base = sbase + SM_B + (uint32_t)buf * BBUF;
#pragma unroll
        for (int kt = 0; kt < 4; kt++) {
            uint32_t koff = (uint32_t)kt * 32;    // 16 halves
            uint32_t a0[4], a1[4], bb[10];
            ldsm_x4(a0[0], a0[1], a0[2], a0[3], a_ad0 + koff);
            ldsm_x4(a1[0], a1[1], a1[2], a1[3], a_ad1 + koff);
            ldsm_x4(bb[0], bb[1], bb[2], bb[3], b_base + b_off_p + koff);
            ldsm_x4(bb[4], bb[5], bb[6], bb[7],
                    b_base + b_off_p + 16 * BSTR * 2 + koff);
            if (nb == 0)          // nt=4 exists only for the nb==0 warps
                ldsm_x2(bb[8], bb[9], b_base + b_off_2 + koff);
#pragma unroll
            for (int nt = 0; nt < 5; nt++) {
                if (nt == 4 && nb != 0) continue;
                uint32_t b0 = bb[2 * nt], b1 = bb[2 * nt + 1];
                asm volatile(
                    "mma.sync.aligned.m16n8k16.row.col.f32.f16.f16.f32 "
                    "{%0,%1,%2,%3}, {%4,%5,%6,%7}, {%8,%9}, {%0,%1,%2,%3};\n"
                    : "+f"(acc[0][nt][0]), "+f"(acc[0][nt][1]),
                      "+f"(acc[0][nt][2]), "+f"(acc[0][nt][3])
                    : "r"(a0[0]), "r"(a0[1]), "r"(a0[2]), "r"(a0[3]),
                      "r"(b0), "r"(b1));
                asm volatile(
                    "mma.sync.aligned.m16n8k16.row.col.f32.f16.f16.f32 "
                    "{%0,%1,%2,%3}, {%4,%5,%6,%7}, {%8,%9}, {%0,%1,%2,%3};\n"
                    : "+f"(acc[1][nt][0]), "+f"(acc[1][nt][1]),
                      "+f"(acc[1][nt][2]), "+f"(acc[1][nt][3])
                    : "r"(a1[0]), "r"(a1[1]), "r"(a1[2]), "r"(a1[3]),
                      "r"(b0), "r"(b1));
            }
        }
    }

    // ---- write partials: nums (cols 0..63) + den (logical col 64)
    float* pp = &g_part[((size_t)split * NN + i0) * PART_STRIDE];
#pragma unroll
    for (int m = 0; m < 2; m++) {
        int r0 = mb + m * 16 + g, r1 = r0 + 8;
#pragma unroll
        for (int nt = 0; nt < 5; nt++) {
            if (nt == 4 && nb != 0) continue;
            int nb2 = nb + nt * 8 + 2 * tig;
            if (nb2 < 64) {
                pp[(size_t)r0 * PART_STRIDE + nb2] = acc[m][nt][0];
                pp[(size_t)r1 * PART_STRIDE + nb2] = acc[m][nt][2];
            }
            if (nb2 + 1 < 64) {
                pp[(size_t)r0 * PART_STRIDE + nb2 + 1] = acc[m][nt][1];
                pp[(size_t)r1 * PART_STRIDE + nb2 + 1] = acc[m][nt][3];
            }
        }
        if (nb == 40 && tig == 0) {    // col 64 = 40 + 3*8 + 0
            pp[(size_t)r0 * PART_STRIDE + 64] = acc[m][3][0];
            pp[(size_t)r1 * PART_STRIDE + 64] = acc[m][3][2];
        }
    }
}

// ---------------------------------------------------------------------------
// Kernel 4: reduce partials across splits + elu.  Thread = (i, 16 cols):
// 20 independent loads in flight (MLP 20).  Resets g_m2key for next replay.
// ---------------------------------------------------------------------------
__global__ __launch_bounds__(256) void k_reduce(float* __restrict__ out)
{
    int idx = blockIdx.x * 256 + threadIdx.x;   // 0 .. NN*4
    int i = idx >> 2;
    int c16 = (idx & 3) * 16;

    float4 num[4];
#pragma unroll
    for (int u = 0; u < 4; u++) num[u] = make_float4(0.f, 0.f, 0.f, 0.f);
    float den = 0.f;
#pragma unroll
    for (int s = 0; s < NSPLIT; s++) {
        const float* pp = &g_part[((size_t)s * NN + i) * PART_STRIDE];
#pragma unroll
        for (int u = 0; u < 4; u++) {
            float4 v = *(const float4*)(pp + c16 + 4 * u);
            num[u].x += v.x; num[u].y += v.y; num[u].z += v.z; num[u].w += v.w;
        }
        den += pp[64];
    }
#pragma unroll
    for (int u = 0; u < 4; u++) {
        float4 r;
        r.x = elu_f(num[u].x / den);
        r.y = elu_f(num[u].y / den);
        r.z = elu_f(num[u].z / den);
        r.w = elu_f(num[u].w / den);
        *(float4*)&out[(size_t)i * FOUT + c16 + 4 * u] = r;
    }

    if (blockIdx.x == 0 && threadIdx.x == 0) g_m2key = 0u;  // for next replay
}

// ---------------------------------------------------------------------------
extern "C" void kernel_launch(void* const* d_in, const int* in_sizes, int n_in,
                              void* d_out, int out_size)
{
    const float* h   = (const float*)d_in[0];
    const int*   adj = (const int*)d_in[1];
    const float* W   = (const float*)d_in[2];
    const float* a   = (const float*)d_in[3];
    float* out = (float*)d_out;

    cudaFuncSetAttribute(k_gat, cudaFuncAttributeMaxDynamicSharedMemorySize,
                         SMEM_TOTAL);

    k_gemm_wh<<<NN / 64, 256>>>(h, W, a);
    k_consts<<<NN / 256, 256>>>();
    k_gat<<<(NN / BM) * NSPLIT, 256, SMEM_TOTAL>>>(adj);
    k_reduce<<<NN * 4 / 256, 256>>>(out);
}

// round 12
// speedup vs baseline: 1.1454x; 1.1454x over previous
#include <cuda_runtime.h>
#include <cuda_fp16.h>
#include <math.h>
#include <stdint.h>

#define NN 8192
#define FIN 256
#define FOUT 64
#define LRALPHA 0.2f

#define BM 128
#define BK 64
#define NB 80               // B n-rows: 64 out + ones(64) + zeros(65..79)
#define ASTR 72             // A SMEM stride (halves)
#define BSTR 72             // B SMEM stride (halves)
#define NSPLIT 4
#define JCHUNK (NN / NSPLIT)        // 2048
#define NTILES (JCHUNK / BK)        // 32
#define PART_STRIDE 72

// ---- persistent scratch (no allocations allowed) ----
__device__ __align__(16) __half g_Wht[(size_t)NB * NN];   // transposed fp16 Wh + ones/zeros
__device__ __align__(16) float4 g_rowc[NN];  // (f1, exp(f1-m), exp(.2f1-m), 0)
__device__ __align__(16) float g_cpl[3 * NN]; // planar: [f2][exp(f2)][exp(.2f2)]
__device__ float g_f1[NN];
__device__ float g_f2[NN];
__device__ unsigned int g_m2key;
__device__ __align__(16) float g_part[(size_t)NSPLIT * NN * PART_STRIDE];

__device__ __forceinline__ float elu_f(float x) {
    return x > 0.f ? x : expm1f(x);
}
__device__ __forceinline__ unsigned int fkey(float x) {
    unsigned int b = __float_as_uint(x);
    return (b & 0x80000000u) ? ~b : (b | 0x80000000u);
}
__device__ __forceinline__ float fdecode(unsigned int k) {
    return __uint_as_float((k & 0x80000000u) ? (k & 0x7fffffffu) : ~k);
}
__device__ __forceinline__ void cp_async16(uint32_t smem_addr, const void* gptr) {
    asm volatile("cp.async.cg.shared.global [%0], [%1], 16;\n"
                 :: "r"(smem_addr), "l"(gptr));
}
__device__ __forceinline__ void cp_commit() {
    asm volatile("cp.async.commit_group;\n" ::: "memory");
}
__device__ __forceinline__ void cp_wait1() {
    asm volatile("cp.async.wait_group 1;\n" ::: "memory");
}
__device__ __forceinline__ void cp_wait0() {
    asm volatile("cp.async.wait_group 0;\n" ::: "memory");
}
__device__ __forceinline__ void ldsm_x4(uint32_t& r0, uint32_t& r1,
                                        uint32_t& r2, uint32_t& r3, uint32_t a) {
    asm volatile("ldmatrix.sync.aligned.m8n8.x4.shared.b16 {%0,%1,%2,%3}, [%4];"
                 : "=r"(r0), "=r"(r1), "=r"(r2), "=r"(r3) : "r"(a));
}
__device__ __forceinline__ void ldsm_x2(uint32_t& r0, uint32_t& r1, uint32_t a) {
    asm volatile("ldmatrix.sync.aligned.m8n8.x2.shared.b16 {%0,%1}, [%2];"
                 : "=r"(r0), "=r"(r1) : "r"(a));
}

// ---------------------------------------------------------------------------
// Kernel 1: g_Wht[c][i] = fp16((h @ W)[i][c]); row 64 = 1; rows 65..79 = 0.
// (R10 version, unchanged.)
// ---------------------------------------------------------------------------
__global__ __launch_bounds__(256) void k_gemm_wh(
    const float* __restrict__ h, const float* __restrict__ W)
{
    __shared__ float hs[16][68];
    __shared__ float wt2[64][68];
    __shared__ float ts[64][17];   // transpose staging [c][r_local]

    int t = threadIdx.x;
    int c = t & 63;
    int ry = t >> 6;               // 0..3 (staging)
    int i0 = blockIdx.x * 16;

    int rr = t >> 4;               // 0..15 (compute row)
    int cg = t & 15;               // 0..15 (compute col-group)

    if (blockIdx.x == 0 && t == 0) g_m2key = 0u;  // reset max key each replay

    float4 acc = make_float4(0.f, 0.f, 0.f, 0.f);

    for (int kt = 0; kt < FIN; kt += 64) {
        __syncthreads();
#pragma unroll
        for (int it = 0; it < 4; it++) {
            int r = ry + 4 * it;
            hs[r][c] = h[(size_t)(i0 + r) * FIN + kt + c];
        }
#pragma unroll
        for (int it = 0; it < 16; it++) {
            int r = ry + 4 * it;
            wt2[r][c] = W[(size_t)(kt + r) * FOUT + c];
        }
        __syncthreads();
#pragma unroll
        for (int k4 = 0; k4 < 16; k4++) {
            float4 hv = *(const float4*)&hs[rr][k4 * 4];   // broadcast
            float4 w0 = *(const float4*)&wt2[k4 * 4 + 0][cg * 4];
            float4 w1 = *(const float4*)&wt2[k4 * 4 + 1][cg * 4];
            float4 w2 = *(const float4*)&wt2[k4 * 4 + 2][cg * 4];
            float4 w3 = *(const float4*)&wt2[k4 * 4 + 3][cg * 4];
            acc.x += hv.x * w0.x + hv.y * w1.x + hv.z * w2.x + hv.w * w3.x;
            acc.y += hv.x * w0.y + hv.y * w1.y + hv.z * w2.y + hv.w * w3.y;
            acc.z += hv.x * w0.z + hv.y * w1.z + hv.z * w2.z + hv.w * w3.z;
            acc.w += hv.x * w0.w + hv.y * w1.w + hv.z * w2.w + hv.w * w3.w;
        }
    }
    // stage for transpose: ts[col][row]
    ts[cg * 4 + 0][rr] = acc.x;
    ts[cg * 4 + 1][rr] = acc.y;
    ts[cg * 4 + 2][rr] = acc.z;
    ts[cg * 4 + 3][rr] = acc.w;
    __syncthreads();

    // transposed fp16 write
    {
        int c2 = t >> 2, q = t & 3;
        __half2 h0 = __floats2half2_rn(ts[c2][q * 4 + 0], ts[c2][q * 4 + 1]);
        __half2 h1 = __floats2half2_rn(ts[c2][q * 4 + 2], ts[c2][q * 4 + 3]);
        __half2* dst = (__half2*)&g_Wht[(size_t)c2 * NN + i0 + q * 4];
        dst[0] = h0;
        dst[1] = h1;
    }
    // ones / zero rows 64..79 for this i-slice
    {
        int rz = 64 + (t >> 4), ii = t & 15;
        g_Wht[(size_t)rz * NN + i0 + ii] = (rz == 64) ? __float2half(1.0f)
                                                      : __float2half(0.0f);
    }
}

// ---------------------------------------------------------------------------
// Kernel 2: f1/f2 per node + global max of f2.  (R10 version, unchanged.)
// ---------------------------------------------------------------------------
__global__ __launch_bounds__(256) void k_fvec(const float* __restrict__ a)
{
    int i = blockIdx.x * 256 + threadIdx.x;
    float s1 = 0.f, s2 = 0.f;
#pragma unroll 8
    for (int c = 0; c < 64; c++) {
        float v = __half2float(g_Wht[(size_t)c * NN + i]);
        s1 += v * __ldg(&a[c]);
        s2 += v * __ldg(&a[64 + c]);
    }
    g_f1[i] = s1;
    g_f2[i] = s2;
    float m = s2;
#pragma unroll
    for (int o = 16; o > 0; o >>= 1)
        m = fmaxf(m, __shfl_xor_sync(0xffffffffu, m, o));
    if ((threadIdx.x & 31) == 0) atomicMax(&g_m2key, fkey(m));
}

// ---------------------------------------------------------------------------
// Kernel 3: row constants (AoS) + column constants (PLANAR for k_gat).
// ---------------------------------------------------------------------------
__global__ __launch_bounds__(256) void k_consts()
{
    int i = blockIdx.x * 256 + threadIdx.x;
    float M2 = fdecode(g_m2key);
    float f1 = g_f1[i], f2 = g_f2[i];
    float z = f1 + M2;
    float m = (z > 0.f) ? z : LRALPHA * z;
    g_rowc[i] = make_float4(f1, expf(f1 - m), expf(LRALPHA * f1 - m), 0.f);
    g_cpl[i]          = f2;
    g_cpl[NN + i]     = expf(f2);
    g_cpl[2 * NN + i] = expf(LRALPHA * f2);
}

// ---------------------------------------------------------------------------
// Kernel 4: fused masked-softmax attention partials (fp16 m16n8k16 MMA,
// ldmatrix fragments, R6/R10 pipeline schedule — UNCHANGED).
// Single change vs R10: adjacency via LDG.128 (8 x int4 per thread: lane owns
// 4 cols x 8 rows) + planar colc smem (3 x 64-float planes per buffer).
// grid = 64 i-blocks x 4 j-splits = 256 CTAs, 2 CTAs/SM.
// SMEM (bytes):
//   [0,     18432)  half  A[128][72]
//   [18432, 41472)  half  B[2][80][72]
//   [41472, 43008)  float colc[2][3][64]   (planar)
//   [43008, 45056)  float4 rowcs[128]
// ---------------------------------------------------------------------------
#define SM_A     0
#define SM_B     18432
#define SM_COLC  41472
#define SM_ROWC  43008
#define SMEM_TOTAL 45056
#define BBUF (NB * BSTR * 2)       // 11520

__global__ __launch_bounds__(256, 2) void k_gat(const int* __restrict__ adj)
{
    extern __shared__ __align__(16) char smem[];
    uint32_t sbase = (uint32_t)__cvta_generic_to_shared(smem);

    int t = threadIdx.x;
    int warp = t >> 5, lane = t & 31;
    int i0 = (blockIdx.x >> 2) * BM;
    int split = blockIdx.x & 3;
    int jstart = split * JCHUNK;

    // fixed row constants for the whole CTA
    if (t < 128) ((float4*)(smem + SM_ROWC))[t] = g_rowc[i0 + t];

    // w-gen mapping: warp -> rows 16w..16w+15; lane: rp = l>>4 row parity,
    // cq = l&15 -> cols 4cq..4cq+3.  Thread rows: wrow0 + rp + 2k, k=0..7.
    int wrow0 = warp * 16;
    int rp = lane >> 4;
    int cq = lane & 15;
    const int* aptr = adj + (size_t)(i0 + wrow0 + rp) * NN + 4 * cq;

    // MMA mapping
    int mb = (warp & 3) * 32;      // 32 rows (2 m-tiles)
    int nb = (warp >> 2) * 40;     // 40 cols (5 n-tiles)
    int g = lane >> 2, tig = lane & 3;

    // ldmatrix lane addresses
    uint32_t a_ad0 = sbase + SM_A +
        (uint32_t)(((mb + (lane & 15)) * ASTR + ((lane >> 4) << 3)) * 2);
    uint32_t a_ad1 = a_ad0 + 16 * ASTR * 2;
    uint32_t b_off_p = (uint32_t)(((nb + ((lane >> 4) << 3) + (lane & 7)) * BSTR
                                   + (((lane >> 3) & 1) << 3)) * 2);
    uint32_t b_off_2 = (uint32_t)(((nb + 32 + (lane & 7)) * BSTR
                                   + (((lane >> 3) & 1) << 3)) * 2);

    float acc[2][5][4];
#pragma unroll
    for (int m = 0; m < 2; m++)
#pragma unroll
        for (int n = 0; n < 5; n++)
#pragma unroll
            for (int x = 0; x < 4; x++) acc[m][n][x] = 0.f;

    // ---- prologue: B(0)+colc(0) cp.async into buf 0; adj(0) -> registers
    {
#pragma unroll
        for (int it = 0; it < 3; it++) {
            int l = t + 256 * it;
            if (l < 640) {
                int n = l >> 3, kc = l & 7;
                cp_async16(sbase + SM_B + (uint32_t)(n * (BSTR * 2) + kc * 16),
                           &g_Wht[(size_t)n * NN + jstart + kc * 8]);
            }
        }
        if (t < 48) {
            int p = t >> 4, x = t & 15;
            cp_async16(sbase + SM_COLC + (uint32_t)(p * 256 + x * 16),
                       &g_cpl[(size_t)p * NN + jstart + x * 4]);
        }
        cp_commit();
    }

    int4 av[8];
#pragma unroll
    for (int k = 0; k < 8; k++)
        av[k] = __ldcs((const int4*)(aptr + (size_t)(2 * k) * NN + jstart));

    for (int tt = 0; tt < NTILES; tt++) {
        int buf = tt & 1;
        int j0 = jstart + tt * BK;

        // 1. all warps done with MMA(tt-1) (reads B[buf^1]) before refill
        __syncthreads();

        // 2. issue B(tt+1)/colc(tt+1) into buf^1
        if (tt + 1 < NTILES) {
            int jn = j0 + BK;
            uint32_t bd = sbase + SM_B + (uint32_t)(buf ^ 1) * BBUF;
            uint32_t cd = sbase + SM_COLC + (uint32_t)(buf ^ 1) * 768;
#pragma unroll
            for (int it = 0; it < 3; it++) {
                int l = t + 256 * it;
                if (l < 640) {
                    int n = l >> 3, kc = l & 7;
                    cp_async16(bd + (uint32_t)(n * (BSTR * 2) + kc * 16),
                               &g_Wht[(size_t)n * NN + jn + kc * 8]);
                }
            }
            if (t < 48) {
                int p = t >> 4, x = t & 15;
                cp_async16(cd + (uint32_t)(p * 256 + x * 16),
                           &g_cpl[(size_t)p * NN + jn + x * 4]);
            }
            cp_commit();
            cp_wait1();   // B(tt)/colc(tt) complete; tt+1 in flight
        } else {
            cp_wait0();
        }

        // 3. visibility of B(tt)/colc(tt)
        __syncthreads();

        // 4. w-gen: registers(adj int4) + planar colc + rowc -> fp16 A[128][64]
        {
            const float* cp0 = (const float*)(smem + SM_COLC + buf * 768);
            float4 f2v = *(const float4*)(cp0 + 4 * cq);
            float4 yv  = *(const float4*)(cp0 + 64 + 4 * cq);
            float4 zv  = *(const float4*)(cp0 + 128 + 4 * cq);
            const float4* rw = (const float4*)(smem + SM_ROWC) + wrow0;
            __half* Ah = (__half*)(smem + SM_A);
#pragma unroll
            for (int k = 0; k < 8; k++) {
                int row = rp + 2 * k;
                float4 rc = rw[row];               // LDS 2-way broadcast
                int4 a4 = av[k];
                float w0 = ((rc.x + f2v.x) > 0.f) ? rc.y * yv.x : rc.z * zv.x;
                float w1 = ((rc.x + f2v.y) > 0.f) ? rc.y * yv.y : rc.z * zv.y;
                float w2 = ((rc.x + f2v.z) > 0.f) ? rc.y * yv.z : rc.z * zv.z;
                float w3 = ((rc.x + f2v.w) > 0.f) ? rc.y * yv.w : rc.z * zv.w;
                w0 = a4.x ? w0 : 0.f;
                w1 = a4.y ? w1 : 0.f;
                w2 = a4.z ? w2 : 0.f;
                w3 = a4.w ? w3 : 0.f;
                __half2 p0 = __floats2half2_rn(w0, w1);
                __half2 p1 = __floats2half2_rn(w2, w3);
                uint2 pk;
                pk.x = *(uint32_t*)&p0;
                pk.y = *(uint32_t*)&p1;
                *(uint2*)&Ah[(wrow0 + row) * ASTR + 4 * cq] = pk;   // STS.64
            }
        }

        // 5. stream adj(tt+1) into registers (flies over sync + MMA)
        if (tt + 1 < NTILES) {
            int jn = j0 + BK;
#pragma unroll
            for (int k = 0; k < 8; k++)
                av[k] = __ldcs((const int4*)(aptr + (size_t)(2 * k) * NN + jn));
        }

        // 6. A visible
        __syncthreads();

        // 7. MMA: 4 k-steps x (2 m-tiles x 5 n-tiles), ldmatrix fragments
        uint32_t b_base = sbase + SM_B + (uint32_t)buf * BBUF;
#pragma unroll
        for (int kt = 0; kt < 4; kt++) {
            uint32_t koff = (uint32_t)kt * 32;    // 16 halves
            uint32_t a0[4], a1[4], bb[10];
            ldsm_x4(a0[0], a0[1], a0[2], a0[3], a_ad0 + koff);
            ldsm_x4(a1[0], a1[1], a1[2], a1[3], a_ad1 + koff);
            ldsm_x4(bb[0], bb[1], bb[2], bb[3], b_base + b_off_p + koff);
            ldsm_x4(bb[4], bb[5], bb[6], bb[7],
                    b_base + b_off_p + 16 * BSTR * 2 + koff);
            ldsm_x2(bb[8], bb[9], b_base + b_off_2 + koff);
#pragma unroll
            for (int nt = 0; nt < 5; nt++) {
                uint32_t b0 = bb[2 * nt], b1 = bb[2 * nt + 1];
                asm volatile(
                    "mma.sync.aligned.m16n8k16.row.col.f32.f16.f16.f32 "
                    "{%0,%1,%2,%3}, {%4,%5,%6,%7}, {%8,%9}, {%0,%1,%2,%3};\n"
                    : "+f"(acc[0][nt][0]), "+f"(acc[0][nt][1]),
                      "+f"(acc[0][nt][2]), "+f"(acc[0][nt][3])
                    : "r"(a0[0]), "r"(a0[1]), "r"(a0[2]), "r"(a0[3]),
                      "r"(b0), "r"(b1));
                asm volatile(
                    "mma.sync.aligned.m16n8k16.row.col.f32.f16.f16.f32 "
                    "{%0,%1,%2,%3}, {%4,%5,%6,%7}, {%8,%9}, {%0,%1,%2,%3};\n"
                    : "+f"(acc[1][nt][0]), "+f"(acc[1][nt][1]),
                      "+f"(acc[1][nt][2]), "+f"(acc[1][nt][3])
                    : "r"(a1[0]), "r"(a1[1]), "r"(a1[2]), "r"(a1[3]),
                      "r"(b0), "r"(b1));
            }
        }
    }

    // ---- write partials: nums (cols 0..63) + den (logical col 64)
    float* pp = &g_part[((size_t)split * NN + i0) * PART_STRIDE];
#pragma unroll
    for (int m = 0; m < 2; m++) {
        int r0 = mb + m * 16 + g, r1 = r0 + 8;
#pragma unroll
        for (int nt = 0; nt < 5; nt++) {
            int nb2 = nb + nt * 8 + 2 * tig;
            if (nb2 < 64) {
                pp[(size_t)r0 * PART_STRIDE + nb2] = acc[m][nt][0];
                pp[(size_t)r1 * PART_STRIDE + nb2] = acc[m][nt][2];
            }
            if (nb2 + 1 < 64) {
                pp[(size_t)r0 * PART_STRIDE + nb2 + 1] = acc[m][nt][1];
                pp[(size_t)r1 * PART_STRIDE + nb2 + 1] = acc[m][nt][3];
            }
        }
        if (nb == 40 && tig == 0) {    // col 64 = 40 + 3*8 + 0
            pp[(size_t)r0 * PART_STRIDE + 64] = acc[m][3][0];
            pp[(size_t)r1 * PART_STRIDE + 64] = acc[m][3][2];
        }
    }
}

// ---------------------------------------------------------------------------
// Kernel 5: reduce partials across splits + elu (R10 version, unchanged).
// ---------------------------------------------------------------------------
__global__ __launch_bounds__(256) void k_reduce(float* __restrict__ out)
{
    int idx = blockIdx.x * 256 + threadIdx.x;   // 0 .. NN*16
    int i = idx >> 4;
    int c4 = (idx & 15) * 4;

    float4 num = make_float4(0.f, 0.f, 0.f, 0.f);
    float den = 0.f;
#pragma unroll
    for (int s = 0; s < NSPLIT; s++) {
        const float* pp = &g_part[((size_t)s * NN + i) * PART_STRIDE];
        float4 v = *(const float4*)(pp + c4);
        num.x += v.x; num.y += v.y; num.z += v.z; num.w += v.w;
        den += pp[64];
    }
    float4 r;
    r.x = elu_f(num.x / den);
    r.y = elu_f(num.y / den);
    r.z = elu_f(num.z / den);
    r.w = elu_f(num.w / den);
    *(float4*)&out[(size_t)i * FOUT + c4] = r;
}

// ---------------------------------------------------------------------------
extern "C" void kernel_launch(void* const* d_in, const int* in_sizes, int n_in,
                              void* d_out, int out_size)
{
    const float* h   = (const float*)d_in[0];
    const int*   adj = (const int*)d_in[1];
    const float* W   = (const float*)d_in[2];
    const float* a   = (const float*)d_in[3];
    float* out = (float*)d_out;

    cudaFuncSetAttribute(k_gat, cudaFuncAttributeMaxDynamicSharedMemorySize,
                         SMEM_TOTAL);

    k_gemm_wh<<<NN / 16, 256>>>(h, W);
    k_fvec<<<NN / 256, 256>>>(a);
    k_consts<<<NN / 256, 256>>>();
    k_gat<<<(NN / BM) * NSPLIT, 256, SMEM_TOTAL>>>(adj);
    k_reduce<<<NN * 16 / 256, 256>>>(out);
}

// round 13
// speedup vs baseline: 1.3720x; 1.1978x over previous
#include <cuda_runtime.h>
#include <cuda_fp16.h>
#include <math.h>
#include <stdint.h>

#define NN 8192
#define FIN 256
#define FOUT 64
#define LRALPHA 0.2f

#define BM 128
#define BK 64
#define NB 80               // B n-rows: 64 out + ones(64) + zeros(65..79)
#define ASTR 72             // A SMEM stride (halves)
#define BSTR 72             // B SMEM stride (halves)
#define NSPLIT 4
#define JCHUNK (NN / NSPLIT)        // 2048
#define NTILES (JCHUNK / BK)        // 32
#define PART_STRIDE 72

// ---- persistent scratch (no allocations allowed) ----
__device__ __align__(16) __half g_Wht[(size_t)NB * NN];   // transposed fp16 Wh + ones/zeros
__device__ __align__(16) float4 g_rowc[NN];  // (f1, exp(f1-m), exp(.2f1-m), 0)
__device__ __align__(16) float g_cpl[3 * NN]; // planar: [f2][exp(f2)][exp(.2f2)]
__device__ float g_f1[NN];
__device__ float g_f2[NN];
__device__ unsigned int g_m2key = 0u;        // reset at end of k_reduce (prev replay)
__device__ __align__(16) float g_part[(size_t)NSPLIT * NN * PART_STRIDE];

__device__ __forceinline__ float elu_f(float x) {
    return x > 0.f ? x : expm1f(x);
}
__device__ __forceinline__ unsigned int fkey(float x) {
    unsigned int b = __float_as_uint(x);
    return (b & 0x80000000u) ? ~b : (b | 0x80000000u);
}
__device__ __forceinline__ float fdecode(unsigned int k) {
    return __uint_as_float((k & 0x80000000u) ? (k & 0x7fffffffu) : ~k);
}
__device__ __forceinline__ void cp_async16(uint32_t smem_addr, const void* gptr) {
    asm volatile("cp.async.cg.shared.global [%0], [%1], 16;\n"
                 :: "r"(smem_addr), "l"(gptr));
}
__device__ __forceinline__ void cp_commit() {
    asm volatile("cp.async.commit_group;\n" ::: "memory");
}
__device__ __forceinline__ void cp_wait1() {
    asm volatile("cp.async.wait_group 1;\n" ::: "memory");
}
__device__ __forceinline__ void cp_wait0() {
    asm volatile("cp.async.wait_group 0;\n" ::: "memory");
}
__device__ __forceinline__ void ldsm_x4(uint32_t& r0, uint32_t& r1,
                                        uint32_t& r2, uint32_t& r3, uint32_t a) {
    asm volatile("ldmatrix.sync.aligned.m8n8.x4.shared.b16 {%0,%1,%2,%3}, [%4];"
                 : "=r"(r0), "=r"(r1), "=r"(r2), "=r"(r3) : "r"(a));
}
__device__ __forceinline__ void ldsm_x2(uint32_t& r0, uint32_t& r1, uint32_t a) {
    asm volatile("ldmatrix.sync.aligned.m8n8.x2.shared.b16 {%0,%1}, [%2];"
                 : "=r"(r0), "=r"(r1) : "r"(a));
}

// ---------------------------------------------------------------------------
// Kernel 1: Wh = h @ W (fp32), transposed fp16 store to g_Wht; rows 64..79 =
// ones/zeros.  Fused epilogue: f1 = Wh.a1, f2 = Wh.a2, M2 = max f2 (atomicMax).
// Block = 64 rows, grid 128.  Thread = (rs = t>>4: 4 rows) x (cg = t&15: 4 cols).
// LDS traffic 2 B/FFMA (was 5).  (Verified in R11; only the ones/zeros rows
// extended to 64..79 for NB=80.)
// ---------------------------------------------------------------------------
__global__ __launch_bounds__(256) void k_gemm_wh(
    const float* __restrict__ h, const float* __restrict__ W,
    const float* __restrict__ a)
{
    __shared__ float hs[64][68];
    __shared__ float wt2[64][68];
    __shared__ unsigned int smax;
    float* ts = &hs[0][0];         // alias: transpose staging [c][r], stride 65

    int t = threadIdx.x;
    int i0 = blockIdx.x * 64;
    int cg = t & 15;               // col-group: cols 4cg..4cg+3
    int rs = t >> 4;               // row-slot : rows 4rs..4rs+3

    if (t == 0) smax = 0u;

    float4 acc[4];
#pragma unroll
    for (int q = 0; q < 4; q++) acc[q] = make_float4(0.f, 0.f, 0.f, 0.f);

    for (int kt = 0; kt < FIN; kt += 64) {
        __syncthreads();
#pragma unroll
        for (int it = 0; it < 16; it++) {
            int l = t + 256 * it;
            int r = l >> 6, c = l & 63;
            hs[r][c]  = h[(size_t)(i0 + r) * FIN + kt + c];
            wt2[r][c] = W[(size_t)(kt + r) * FOUT + c];
        }
        __syncthreads();
#pragma unroll
        for (int k4 = 0; k4 < 16; k4++) {
            float4 w0 = *(const float4*)&wt2[k4 * 4 + 0][cg * 4];
            float4 w1 = *(const float4*)&wt2[k4 * 4 + 1][cg * 4];
            float4 w2 = *(const float4*)&wt2[k4 * 4 + 2][cg * 4];
            float4 w3 = *(const float4*)&wt2[k4 * 4 + 3][cg * 4];
#pragma unroll
            for (int q = 0; q < 4; q++) {
                float4 hv = *(const float4*)&hs[rs * 4 + q][k4 * 4];  // broadcast
                acc[q].x += hv.x * w0.x + hv.y * w1.x + hv.z * w2.x + hv.w * w3.x;
                acc[q].y += hv.x * w0.y + hv.y * w1.y + hv.z * w2.y + hv.w * w3.y;
                acc[q].z += hv.x * w0.z + hv.y * w1.z + hv.z * w2.z + hv.w * w3.z;
                acc[q].w += hv.x * w0.w + hv.y * w1.w + hv.z * w2.w + hv.w * w3.w;
            }
        }
    }

    // ---- fused f1/f2: per-row dots with a1/a2, reduce across the 16 cg lanes
    {
        float4 a1v = *(const float4*)&a[4 * cg];
        float4 a2v = *(const float4*)&a[64 + 4 * cg];
        float s1[4], s2[4];
#pragma unroll
        for (int q = 0; q < 4; q++) {
            s1[q] = acc[q].x * a1v.x + acc[q].y * a1v.y
                  + acc[q].z * a1v.z + acc[q].w * a1v.w;
            s2[q] = acc[q].x * a2v.x + acc[q].y * a2v.y
                  + acc[q].z * a2v.z + acc[q].w * a2v.w;
        }
#pragma unroll
        for (int o = 8; o > 0; o >>= 1) {
#pragma unroll
            for (int q = 0; q < 4; q++) {
                s1[q] += __shfl_xor_sync(0xffffffffu, s1[q], o);
                s2[q] += __shfl_xor_sync(0xffffffffu, s2[q], o);
            }
        }
        if (cg == 0) {
            float mm = -1e30f;
#pragma unroll
            for (int q = 0; q < 4; q++) {
                g_f1[i0 + rs * 4 + q] = s1[q];
                g_f2[i0 + rs * 4 + q] = s2[q];
                mm = fmaxf(mm, s2[q]);
            }
            atomicMax(&smax, fkey(mm));
        }
    }
    __syncthreads();               // hs free; smax complete
    if (t == 0) atomicMax(&g_m2key, smax);

    // ---- stage transpose ts[c][r] (stride 65), then fp16 write
#pragma unroll
    for (int q = 0; q < 4; q++) {
        ts[(4 * cg + 0) * 65 + rs * 4 + q] = acc[q].x;
        ts[(4 * cg + 1) * 65 + rs * 4 + q] = acc[q].y;
        ts[(4 * cg + 2) * 65 + rs * 4 + q] = acc[q].z;
        ts[(4 * cg + 3) * 65 + rs * 4 + q] = acc[q].w;
    }
    __syncthreads();
    {
        int c2 = t >> 2, q = t & 3;        // c2: col 0..63, q: 16-row chunk
        __half2 hx[8];
#pragma unroll
        for (int j = 0; j < 8; j++)
            hx[j] = __floats2half2_rn(ts[c2 * 65 + q * 16 + 2 * j],
                                      ts[c2 * 65 + q * 16 + 2 * j + 1]);
        float4* dst = (float4*)&g_Wht[(size_t)c2 * NN + i0 + q * 16];
        dst[0] = *(float4*)&hx[0];
        dst[1] = *(float4*)&hx[4];
    }
    // ones / zero rows 64..79 for this i-slice (4 halves per thread)
    {
        int rz = 64 + (t >> 4), ii = (t & 15) * 4;
        __half v = (rz == 64) ? __float2half(1.0f) : __float2half(0.0f);
        __half2 vv = __halves2half2(v, v);
        *(__half2*)&g_Wht[(size_t)rz * NN + i0 + ii] = vv;
        *(__half2*)&g_Wht[(size_t)rz * NN + i0 + ii + 2] = vv;
    }
}

// ---------------------------------------------------------------------------
// Kernel 2: row constants (AoS) + column constants (PLANAR for k_gat).
// ---------------------------------------------------------------------------
__global__ __launch_bounds__(256) void k_consts()
{
    int i = blockIdx.x * 256 + threadIdx.x;
    float M2 = fdecode(g_m2key);
    float f1 = g_f1[i], f2 = g_f2[i];
    float z = f1 + M2;
    float m = (z > 0.f) ? z : LRALPHA * z;
    g_rowc[i] = make_float4(f1, expf(f1 - m), expf(LRALPHA * f1 - m), 0.f);
    g_cpl[i]          = f2;
    g_cpl[NN + i]     = expf(f2);
    g_cpl[2 * NN + i] = expf(LRALPHA * f2);
}

// ---------------------------------------------------------------------------
// Kernel 3: fused masked-softmax attention partials — BYTE-IDENTICAL to R12.
// SMEM (bytes):
//   [0,     18432)  half  A[128][72]
//   [18432, 41472)  half  B[2][80][72]
//   [41472, 43008)  float colc[2][3][64]   (planar)
//   [43008, 45056)  float4 rowcs[128]
// ---------------------------------------------------------------------------
#define SM_A     0
#define SM_B     18432
#define SM_COLC  41472
#define SM_ROWC  43008
#define SMEM_TOTAL 45056
#define BBUF (NB * BSTR * 2)       // 11520

__global__ __launch_bounds__(256, 2) void k_gat(const int* __restrict__ adj)
{
    extern __shared__ __align__(16) char smem[];
    uint32_t sbase = (uint32_t)__cvta_generic_to_shared(smem);

    int t = threadIdx.x;
    int warp = t >> 5, lane = t & 31;
    int i0 = (blockIdx.x >> 2) * BM;
    int split = blockIdx.x & 3;
    int jstart = split * JCHUNK;

    // fixed row constants for the whole CTA
    if (t < 128) ((float4*)(smem + SM_ROWC))[t] = g_rowc[i0 + t];

    // w-gen mapping: warp -> rows 16w..16w+15; lane: rp = l>>4 row parity,
    // cq = l&15 -> cols 4cq..4cq+3.  Thread rows: wrow0 + rp + 2k, k=0..7.
    int wrow0 = warp * 16;
    int rp = lane >> 4;
    int cq = lane & 15;
    const int* aptr = adj + (size_t)(i0 + wrow0 + rp) * NN + 4 * cq;

    // MMA mapping
    int mb = (warp & 3) * 32;      // 32 rows (2 m-tiles)
    int nb = (warp >> 2) * 40;     // 40 cols (5 n-tiles)
    int g = lane >> 2, tig = lane & 3;

    // ldmatrix lane addresses
    uint32_t a_ad0 = sbase + SM_A +
        (uint32_t)(((mb + (lane & 15)) * ASTR + ((lane >> 4) << 3)) * 2);
    uint32_t a_ad1 = a_ad0 + 16 * ASTR * 2;
    uint32_t b_off_p = (uint32_t)(((nb + ((lane >> 4) << 3) + (lane & 7)) * BSTR
                                   + (((lane >> 3) & 1) << 3)) * 2);
    uint32_t b_off_2 = (uint32_t)(((nb + 32 + (lane & 7)) * BSTR
                                   + (((lane >> 3) & 1) << 3)) * 2);

    float acc[2][5][4];
#pragma unroll
    for (int m = 0; m < 2; m++)
#pragma unroll
        for (int n = 0; n < 5; n++)
#pragma unroll
            for (int x = 0; x < 4; x++) acc[m][n][x] = 0.f;

    // ---- prologue: B(0)+colc(0) cp.async into buf 0; adj(0) -> registers
    {
#pragma unroll
        for (int it = 0; it < 3; it++) {
            int l = t + 256 * it;
            if (l < 640) {
                int n = l >> 3, kc = l & 7;
                cp_async16(sbase + SM_B + (uint32_t)(n * (BSTR * 2) + kc * 16),
                           &g_Wht[(size_t)n * NN + jstart + kc * 8]);
            }
        }
        if (t < 48) {
            int p = t >> 4, x = t & 15;
            cp_async16(sbase + SM_COLC + (uint32_t)(p * 256 + x * 16),
                       &g_cpl[(size_t)p * NN + jstart + x * 4]);
        }
        cp_commit();
    }

    int4 av[8];
#pragma unroll
    for (int k = 0; k < 8; k++)
        av[k] = __ldcs((const int4*)(aptr + (size_t)(2 * k) * NN + jstart));

    for (int tt = 0; tt < NTILES; tt++) {
        int buf = tt & 1;
        int j0 = jstart + tt * BK;

        // 1. all warps done with MMA(tt-1) (reads B[buf^1]) before refill
        __syncthreads();

        // 2. issue B(tt+1)/colc(tt+1) into buf^1
        if (tt + 1 < NTILES) {
            int jn = j0 + BK;
            uint32_t bd = sbase + SM_B + (uint32_t)(buf ^ 1) * BBUF;
            uint32_t cd = sbase + SM_COLC + (uint32_t)(buf ^ 1) * 768;
#pragma unroll
            for (int it = 0; it < 3; it++) {
                int l = t + 256 * it;
                if (l < 640) {
                    int n = l >> 3, kc = l & 7;
                    cp_async16(bd + (uint32_t)(n * (BSTR * 2) + kc * 16),
                               &g_Wht[(size_t)n * NN + jn + kc * 8]);
                }
            }
            if (t < 48) {
                int p = t >> 4, x = t & 15;
                cp_async16(cd + (uint32_t)(p * 256 + x * 16),
                           &g_cpl[(size_t)p * NN + jn + x * 4]);
            }
            cp_commit();
            cp_wait1();   // B(tt)/colc(tt) complete; tt+1 in flight
        } else {
            cp_wait0();
        }

        // 3. visibility of B(tt)/colc(tt)
        __syncthreads();

        // 4. w-gen: registers(adj int4) + planar colc + rowc -> fp16 A[128][64]
        {
            const float* cp0 = (const float*)(smem + SM_COLC + buf * 768);
            float4 f2v = *(const float4*)(cp0 + 4 * cq);
            float4 yv  = *(const float4*)(cp0 + 64 + 4 * cq);
            float4 zv  = *(const float4*)(cp0 + 128 + 4 * cq);
            const float4* rw = (const float4*)(smem + SM_ROWC) + wrow0;
            __half* Ah = (__half*)(smem + SM_A);
#pragma unroll
            for (int k = 0; k < 8; k++) {
                int row = rp + 2 * k;
                float4 rc = rw[row];               // LDS 2-way broadcast
                int4 a4 = av[k];
                float w0 = ((rc.x + f2v.x) > 0.f) ? rc.y * yv.x : rc.z * zv.x;
                float w1 = ((rc.x + f2v.y) > 0.f) ? rc.y * yv.y : rc.z * zv.y;
                float w2 = ((rc.x + f2v.z) > 0.f) ? rc.y * yv.z : rc.z * zv.z;
                float w3 = ((rc.x + f2v.w) > 0.f) ? rc.y * yv.w : rc.z * zv.w;
                w0 = a4.x ? w0 : 0.f;
                w1 = a4.y ? w1 : 0.f;
                w2 = a4.z ? w2 : 0.f;
                w3 = a4.w ? w3 : 0.f;
                __half2 p0 = __floats2half2_rn(w0, w1);
                __half2 p1 = __floats2half2_rn(w2, w3);
                uint2 pk;
                pk.x = *(uint32_t*)&p0;
                pk.y = *(uint32_t*)&p1;
                *(uint2*)&Ah[(wrow0 + row) * ASTR + 4 * cq] = pk;   // STS.64
            }
        }

        // 5. stream adj(tt+1) into registers (flies over sync + MMA)
        if (tt + 1 < NTILES) {
            int jn = j0 + BK;
#pragma unroll
            for (int k = 0; k < 8; k++)
                av[k] = __ldcs((const int4*)(aptr + (size_t)(2 * k) * NN + jn));
        }

        // 6. A visible
        __syncthreads();

        // 7. MMA: 4 k-steps x (2 m-tiles x 5 n-tiles), ldmatrix fragments
        uint32_t b_base = sbase + SM_B + (uint32_t)buf * BBUF;
#pragma unroll
        for (int kt = 0; kt < 4; kt++) {
            uint32_t koff = (uint32_t)kt * 32;    // 16 halves
            uint32_t a0[4], a1[4], bb[10];
            ldsm_x4(a0[0], a0[1], a0[2], a0[3], a_ad0 + koff);
            ldsm_x4(a1[0], a1[1], a1[2], a1[3], a_ad1 + koff);
            ldsm_x4(bb[0], bb[1], bb[2], bb[3], b_base + b_off_p + koff);
            ldsm_x4(bb[4], bb[5], bb[6], bb[7],
                    b_base + b_off_p + 16 * BSTR * 2 + koff);
            ldsm_x2(bb[8], bb[9], b_base + b_off_2 + koff);
#pragma unroll
            for (int nt = 0; nt < 5; nt++) {
                uint32_t b0 = bb[2 * nt], b1 = bb[2 * nt + 1];
                asm volatile(
                    "mma.sync.aligned.m16n8k16.row.col.f32.f16.f16.f32 "
                    "{%0,%1,%2,%3}, {%4,%5,%6,%7}, {%8,%9}, {%0,%1,%2,%3};\n"
                    : "+f"(acc[0][nt][0]), "+f"(acc[0][nt][1]),
                      "+f"(acc[0][nt][2]), "+f"(acc[0][nt][3])
                    : "r"(a0[0]), "r"(a0[1]), "r"(a0[2]), "r"(a0[3]),
                      "r"(b0), "r"(b1));
                asm volatile(
                    "mma.sync.aligned.m16n8k16.row.col.f32.f16.f16.f32 "
                    "{%0,%1,%2,%3}, {%4,%5,%6,%7}, {%8,%9}, {%0,%1,%2,%3};\n"
                    : "+f"(acc[1][nt][0]), "+f"(acc[1][nt][1]),
                      "+f"(acc[1][nt][2]), "+f"(acc[1][nt][3])
                    : "r"(a1[0]), "r"(a1[1]), "r"(a1[2]), "r"(a1[3]),
                      "r"(b0), "r"(b1));
            }
        }
    }

    // ---- write partials: nums (cols 0..63) + den (logical col 64)
    float* pp = &g_part[((size_t)split * NN + i0) * PART_STRIDE];
#pragma unroll
    for (int m = 0; m < 2; m++) {
        int r0 = mb + m * 16 + g, r1 = r0 + 8;
#pragma unroll
        for (int nt = 0; nt < 5; nt++) {
            int nb2 = nb + nt * 8 + 2 * tig;
            if (nb2 < 64) {
                pp[(size_t)r0 * PART_STRIDE + nb2] = acc[m][nt][0];
                pp[(size_t)r1 * PART_STRIDE + nb2] = acc[m][nt][2];
            }
            if (nb2 + 1 < 64) {
                pp[(size_t)r0 * PART_STRIDE + nb2 + 1] = acc[m][nt][1];
                pp[(size_t)r1 * PART_STRIDE + nb2 + 1] = acc[m][nt][3];
            }
        }
        if (nb == 40 && tig == 0) {    // col 64 = 40 + 3*8 + 0
            pp[(size_t)r0 * PART_STRIDE + 64] = acc[m][3][0];
            pp[(size_t)r1 * PART_STRIDE + 64] = acc[m][3][2];
        }
    }
}

// ---------------------------------------------------------------------------
// Kernel 4: reduce partials across splits + elu (R12 version) + g_m2key reset
// for the next graph replay (race-free location, verified in R11).
// ---------------------------------------------------------------------------
__global__ __launch_bounds__(256) void k_reduce(float* __restrict__ out)
{
    int idx = blockIdx.x * 256 + threadIdx.x;   // 0 .. NN*16
    int i = idx >> 4;
    int c4 = (idx & 15) * 4;

    float4 num = make_float4(0.f, 0.f, 0.f, 0.f);
    float den = 0.f;
#pragma unroll
    for (int s = 0; s < NSPLIT; s++) {
        const float* pp = &g_part[((size_t)s * NN + i) * PART_STRIDE];
        float4 v = *(const float4*)(pp + c4);
        num.x += v.x; num.y += v.y; num.z += v.z; num.w += v.w;
        den += pp[64];
    }
    float4 r;
    r.x = elu_f(num.x / den);
    r.y = elu_f(num.y / den);
    r.z = elu_f(num.z / den);
    r.w = elu_f(num.w / den);
    *(float4*)&out[(size_t)i * FOUT + c4] = r;

    if (blockIdx.x == 0 && threadIdx.x == 0) g_m2key = 0u;  // for next replay
}

// ---------------------------------------------------------------------------
extern "C" void kernel_launch(void* const* d_in, const int* in_sizes, int n_in,
                              void* d_out, int out_size)
{
    const float* h   = (const float*)d_in[0];
    const int*   adj = (const int*)d_in[1];
    const float* W   = (const float*)d_in[2];
    const float* a   = (const float*)d_in[3];
    float* out = (float*)d_out;

    cudaFuncSetAttribute(k_gat, cudaFuncAttributeMaxDynamicSharedMemorySize,
                         SMEM_TOTAL);

    k_gemm_wh<<<NN / 64, 256>>>(h, W, a);
    k_consts<<<NN / 256, 256>>>();
    k_gat<<<(NN / BM) * NSPLIT, 256, SMEM_TOTAL>>>(adj);
    k_reduce<<<NN * 16 / 256, 256>>>(out);
}